// round 9
// baseline (speedup 1.0000x reference)
#include <cuda_runtime.h>

// CRF NLL, B=256, S=256, T=128 (126 tags + START/STOP)
// grid=128, 512 threads/CTA = 2 chains x 256 threads. Within a chain, each
// COLUMN j is owned by a lane PAIR: even lane accumulates i in [0,64), odd
// lane i in [64,128), combined by one shfl_xor(1). E-half register-resident
// (32 packed f32x2). Per-chain named barriers; each SMSP hosts 2 warps of
// each chain -> 4-way independent issue supply.
// Scaled-prob recursion: w'_j = (sum_i w_i E[i][j]) * exp(f_j)/(128*w0),
// N += log(w0)+log128;  p_j = N + log w_j recovered at the end.

#define B_    256
#define S_    256
#define T_    128
#define NCTA  128
#define LOG128 4.852030263919617f
#define LN2    0.6931471805599453f
#define HOFF  68        // padded offset of upper i-half in w buffer (floats)

__device__ float g_partial[B_];
__device__ int   g_sched[B_];    // (len << 16) | batch, descending by len
__device__ unsigned g_ticket;    // zero-init; reset by last CTA

#define FMA2(d, a, b, c) \
    asm("fma.rn.f32x2 %0, %1, %2, %3;" : "=l"(d) : "l"(a), "l"(b), "l"(c))
#define ADD2(d, a, b) \
    asm("add.rn.f32x2 %0, %1, %2;" : "=l"(d) : "l"(a), "l"(b))
#define PACK2(d, lo, hi) \
    asm("mov.b64 %0, {%1, %2};" : "=l"(d) : "f"(lo), "f"(hi))
#define UNPACK2(lo, hi, s) \
    asm("mov.b64 {%0, %1}, %2;" : "=f"(lo), "=f"(hi) : "l"(s))
#define BARC(id) \
    asm volatile("bar.sync %0, 256;" :: "r"(id) : "memory")

__device__ __forceinline__ float rcpa(float x) {
    float r; asm("rcp.approx.f32 %0, %1;" : "=f"(r) : "f"(x)); return r;
}
__device__ __forceinline__ float warpMax(float x) {
#pragma unroll
    for (int o = 16; o; o >>= 1) x = fmaxf(x, __shfl_xor_sync(0xffffffffu, x, o));
    return x;
}
__device__ __forceinline__ float warpSum(float x) {
#pragma unroll
    for (int o = 16; o; o >>= 1) x += __shfl_xor_sync(0xffffffffu, x, o);
    return x;
}

// ---- prep: binary-search lengths + bitonic sort (desc) -> g_sched ----
__global__ void prep_kernel(const int* __restrict__ mask) {
    __shared__ unsigned key[B_];
    const int b = threadIdx.x;
    const int* mb = mask + b * S_;
    int lo = S_ / 2, hi = S_;               // len in [S/2, S], prefix mask
    while (lo < hi) {                       // 7 iterations
        int mid = (lo + hi) >> 1;
        if (mb[mid]) lo = mid + 1; else hi = mid;
    }
    key[b] = ((unsigned)lo << 16) | (unsigned)b;
    __syncthreads();
    for (int k = 2; k <= B_; k <<= 1) {
        for (int j = k >> 1; j; j >>= 1) {
            int ixj = b ^ j;
            if (ixj > b) {
                unsigned a = key[b], c = key[ixj];
                bool up = (b & k) == 0;     // descending
                if (up ? (a < c) : (a > c)) { key[b] = c; key[ixj] = a; }
            }
            __syncthreads();
        }
    }
    g_sched[b] = (int)key[b];
}

__global__ void __launch_bounds__(512, 1) crf_kernel(
    const float* __restrict__ feats,       // [B, S, T]
    const float* __restrict__ trans,       // [T, T]
    const void*  __restrict__ tags_raw,    // [B, S] int64 OR int32 (auto-detect)
    float* __restrict__ out)
{
    __shared__ __align__(16) float ws[2][2][2 * HOFF];   // [chain][buf][padded w]
    __shared__ float red[2][24];

    const int tid  = threadIdx.x;
    const int c    = tid >> 8;               // chain slot 0/1
    const int ct   = tid & 255;              // thread within chain
    const int j    = ct >> 1;                // column (0..127)
    const int ih   = ct & 1;                 // i-half (0: i<64, 1: i>=64)
    const int lane = tid & 31;
    const int cw   = (tid >> 5) & 7;         // warp within chain (0..7)
    const int bar  = c + 1;                  // named barrier id
    const int START = T_ - 2, STOP = T_ - 1;
    const int jidx = j + ((j & 64) >> 4);    // padded store index for w_j

    const int sc  = g_sched[2 * blockIdx.x + c];   // adjacent lengths paired
    const int b   = sc & 0xFFFF;
    const int len = sc >> 16;

    // ---- detect tags dtype (int64 from jax-x64, or silently-demoted int32) ----
    int is64;
    {
        const int* t32 = (const int*)tags_raw;
        int bad = 0;
#pragma unroll
        for (int k = 0; k < 16; ++k) bad |= t32[2 * k + 1];
        is64 = (bad == 0);
    }

    // ---- E half-column in registers: rows [ih*64, ih*64+64) of column j ----
    unsigned long long e[32];
    {
        const float* tc = trans + (ih * 64) * T_ + j;
#pragma unroll
        for (int m = 0; m < 32; ++m) {
            float a  = __expf(tc[(2 * m) * T_]);
            float cc = __expf(tc[(2 * m + 1) * T_]);
            PACK2(e[m], a, cc);
        }
    }
    const float tstart = trans[START * T_ + j];
    const float tstop  = trans[j * T_ + STOP];

    const float* fb = feats + (size_t)b * (S_ * T_);

    // ---- init: p0 = feat0 + trans[START];  w0 = exp(p0 - p0[0]);  N = p0[0] ----
    float p0 = fb[j] + tstart;
    if (ct == 0) red[c][0] = p0;
    BARC(bar);
    float N = red[c][0];
    if (ih == 0) ws[c][0][jidx] = __expf(p0 - N);

    const float* fp = fb + T_ + j;
    float fnext = *fp;                       // feat[1]
    int buf = 0;

    for (int t = 1; t < len; ++t) {
        BARC(bar);                           // publishes ws[c][buf]
        const float f = fnext;
        const int sel = (t + 1 < S_) ? T_ : 0;
        fp += sel;
        fnext = *fp;                         // prefetch next feat

        const float* wbase = ws[c][buf];
        const ulonglong2* vv = (const ulonglong2*)(wbase + ih * HOFF);
        float w0 = wbase[0];
        float scale = rcpa(w0) * 0.0078125f;       // 1/(128*w0)
        float ef = __expf(f);                      // overlaps matvec
        N += __logf(w0) + LOG128;                  // off critical path

        unsigned long long a0 = 0, a1 = 0, a2 = 0, a3 = 0;
#pragma unroll
        for (int k = 0; k < 16; k += 2) {
            ulonglong2 x0 = vv[k];
            ulonglong2 x1 = vv[k + 1];
            FMA2(a0, x0.x, e[2 * k],     a0);
            FMA2(a1, x0.y, e[2 * k + 1], a1);
            FMA2(a2, x1.x, e[2 * k + 2], a2);
            FMA2(a3, x1.y, e[2 * k + 3], a3);
        }
        ADD2(a0, a0, a2);
        ADD2(a1, a1, a3);
        ADD2(a0, a0, a1);
        float s0, s1;
        UNPACK2(s0, s1, a0);
        float s = s0 + s1;                   // this thread's i-half sum
        s += __shfl_xor_sync(0xffffffffu, s, 1);   // + partner half

        float wnew = s * (ef * scale);
        buf ^= 1;
        if (ih == 0) ws[c][buf][jidx] = wnew;      // one writer per column
    }

    // ---- final: forward = logsumexp_i(p_i + trans[i,STOP]),  p = N + log w ----
    BARC(bar);                               // final w visible
    float wf = ws[c][buf][jidx];
    float p = N + __logf(wf);                // -inf for START (w=0): fine in max
    float m = warpMax(p);
    if (lane == 0) red[c][cw] = m;
    BARC(bar);
    m = fmaxf(fmaxf(fmaxf(red[c][0], red[c][1]), fmaxf(red[c][2], red[c][3])),
              fmaxf(fmaxf(red[c][4], red[c][5]), fmaxf(red[c][6], red[c][7])));
    float term = wf * __expf(N - m + tstop); // each column counted TWICE (ih 0/1)
    term = warpSum(term);
    if (lane == 0) red[c][8 + cw] = term;
    BARC(bar);
    float ssum = ((red[c][8]  + red[c][9])  + (red[c][10] + red[c][11]))
               + ((red[c][12] + red[c][13]) + (red[c][14] + red[c][15]));
    float fwd = m + __logf(ssum) - LN2;      // correct the 2x duplication

    // ---- gold path score (256 threads of this chain) ----
    const long long* t64 = (const long long*)tags_raw;
    const int*       t32 = (const int*)tags_raw;
    const size_t tbase = (size_t)b * S_;
    float g = 0.f;
    for (int tt = ct; tt < len; tt += 256) {
        int tag  = is64 ? (int)t64[tbase + tt] : t32[tbase + tt];
        int prev = (tt == 0) ? START
                             : (is64 ? (int)t64[tbase + tt - 1] : t32[tbase + tt - 1]);
        g += fb[tt * T_ + tag] + trans[prev * T_ + tag];
    }
    g = warpSum(g);
    if (lane == 0) red[c][16 + cw] = g;
    BARC(bar);

    if (ct == 0) {
        int end_id = is64 ? (int)t64[tbase + len - 1] : t32[tbase + len - 1];
        float gold = ((red[c][16] + red[c][17]) + (red[c][18] + red[c][19]))
                   + ((red[c][20] + red[c][21]) + (red[c][22] + red[c][23]))
                   + trans[end_id * T_ + STOP];
        g_partial[b] = fwd - gold;
        __threadfence();
    }
    __syncthreads();                          // both chains done

    // ---- fused deterministic final reduce (last CTA) ----
    __shared__ unsigned s_rank;
    if (tid == 0) s_rank = atomicAdd(&g_ticket, 1u);
    __syncthreads();
    if (s_rank == NCTA - 1 && tid < 256) {
        __threadfence();                      // acquire: see all g_partial
        float x = g_partial[tid];
        x = warpSum(x);
        __shared__ float sb[8];
        if (lane == 0) sb[tid >> 5] = x;
        __syncwarp();
        asm volatile("bar.sync 3, 256;" ::: "memory");
        if (tid == 0) {
            float s = 0.f;
#pragma unroll
            for (int i = 0; i < 8; ++i) s += sb[i];
            out[0] = s;
            __threadfence();
            atomicExch(&g_ticket, 0u);        // reset for next replay
        }
    }
}

extern "C" void kernel_launch(void* const* d_in, const int* in_sizes, int n_in,
                              void* d_out, int out_size) {
    const float* feats = (const float*)d_in[0];
    const float* trans = (const float*)d_in[1];
    const void*  tags  = d_in[2];
    const int*   mask  = (const int*)d_in[3];

    prep_kernel<<<1, 256>>>(mask);
    crf_kernel<<<NCTA, 512>>>(feats, trans, tags, (float*)d_out);
}

// round 10
// speedup vs baseline: 1.3813x; 1.3813x over previous
#include <cuda_runtime.h>

// CRF NLL, B=256, S=256, T=128 (126 tags + START/STOP)
// grid=148 (one CTA per SM), 256 threads = two independent 128-thread halves
// with per-half NAMED barriers. Schedule (prep kernel): sort chains by length
// desc; 40 longest run SOLO (half 1 empty -> full SMSP issue port), remaining
// 216 paired longest-with-shortest across 108 CTAs (balanced: uniform lengths
// make pair sums nearly constant).
// Scaled-prob recursion, E = exp(transitions) register-resident:
//   w'_j = (sum_i w_i E[i][j]) * exp(f_j) / (128*w0),  N += log(w0)+log128,
//   p_j = N + log w_j recovered once at the end.

#define B_    256
#define S_    256
#define T_    128
#define NCTA  148
#define NSOLO (2 * NCTA - B_)   // 40
#define LOG128 4.852030263919617f

__device__ float g_partial[B_];
__device__ int   g_slot[2 * NCTA];   // (len << 16) | batch, 0 = empty slot
__device__ unsigned g_ticket;        // zero-init; reset by last CTA

#define FMA2(d, a, b, c) \
    asm("fma.rn.f32x2 %0, %1, %2, %3;" : "=l"(d) : "l"(a), "l"(b), "l"(c))
#define ADD2(d, a, b) \
    asm("add.rn.f32x2 %0, %1, %2;" : "=l"(d) : "l"(a), "l"(b))
#define PACK2(d, lo, hi) \
    asm("mov.b64 %0, {%1, %2};" : "=l"(d) : "f"(lo), "f"(hi))
#define UNPACK2(lo, hi, s) \
    asm("mov.b64 {%0, %1}, %2;" : "=f"(lo), "=f"(hi) : "l"(s))
#define BARH(id) \
    asm volatile("bar.sync %0, 128;" :: "r"(id) : "memory")

__device__ __forceinline__ float rcpa(float x) {
    float r; asm("rcp.approx.f32 %0, %1;" : "=f"(r) : "f"(x)); return r;
}
__device__ __forceinline__ float warpMax(float x) {
#pragma unroll
    for (int o = 16; o; o >>= 1) x = fmaxf(x, __shfl_xor_sync(0xffffffffu, x, o));
    return x;
}
__device__ __forceinline__ float warpSum(float x) {
#pragma unroll
    for (int o = 16; o; o >>= 1) x += __shfl_xor_sync(0xffffffffu, x, o);
    return x;
}

// ---- prep: binary-search lengths, sort desc, build solo/pair schedule ----
__global__ void prep_kernel(const int* __restrict__ mask) {
    __shared__ unsigned key[B_];
    const int b = threadIdx.x;
    const int* mb = mask + b * S_;
    int lo = S_ / 2, hi = S_;               // len in [S/2, S], prefix mask
    while (lo < hi) {                       // 7 iterations
        int mid = (lo + hi) >> 1;
        if (mb[mid]) lo = mid + 1; else hi = mid;
    }
    key[b] = ((unsigned)lo << 16) | (unsigned)b;
    __syncthreads();
    for (int k = 2; k <= B_; k <<= 1) {
        for (int j = k >> 1; j; j >>= 1) {
            int ixj = b ^ j;
            if (ixj > b) {
                unsigned a = key[b], c = key[ixj];
                bool up = (b & k) == 0;     // descending
                if (up ? (a < c) : (a > c)) { key[b] = c; key[ixj] = a; }
            }
            __syncthreads();
        }
    }
    // key[0..255] sorted by length desc. Build 296 slots:
    //  CTA c < NSOLO: solo = rank c;   CTA c >= NSOLO (k=c-NSOLO):
    //  half0 = rank NSOLO+k (longer), half1 = rank B-1-k (shorter).
    if (b < NCTA) {
        int s0, s1;
        if (b < NSOLO) { s0 = (int)key[b]; s1 = 0; }
        else {
            int k = b - NSOLO;
            s0 = (int)key[NSOLO + k];
            s1 = (int)key[B_ - 1 - k];
        }
        g_slot[2 * b]     = s0;
        g_slot[2 * b + 1] = s1;
    }
}

__global__ void __launch_bounds__(256, 1) crf_kernel(
    const float* __restrict__ feats,       // [B, S, T]
    const float* __restrict__ trans,       // [T, T]
    const void*  __restrict__ tags_raw,    // [B, S] int64 OR int32 (auto-detect)
    float* __restrict__ out)
{
    __shared__ __align__(16) float ws[2][2][T_];   // [half][buf][j]
    __shared__ float red[2][12];                   // per-half scratch

    const int tid  = threadIdx.x;
    const int h    = tid >> 7;               // half = chain slot
    const int j    = tid & 127;              // output state
    const int lane = tid & 31;
    const int widh = (tid >> 5) & 3;          // warp within half
    const int bar  = h + 1;                   // named barrier id (1 or 2)
    const int START = T_ - 2, STOP = T_ - 1;

    const int sc  = g_slot[2 * blockIdx.x + h];
    const int b   = sc & 0xFFFF;
    const int len = sc >> 16;                 // 0 => empty slot

    // ---- detect tags dtype (int64 from jax-x64, or silently-demoted int32) ----
    int is64;
    {
        const int* t32 = (const int*)tags_raw;
        int bad = 0;
#pragma unroll
        for (int k = 0; k < 16; ++k) bad |= t32[2 * k + 1];
        is64 = (bad == 0);
    }

    if (len > 0) {
        // ---- E column j in registers: e[m]={exp(tr[2m][j]),exp(tr[2m+1][j])} ----
        unsigned long long e[T_ / 2];
        {
            const float* tc = trans + j;
#pragma unroll
            for (int m = 0; m < T_ / 2; ++m) {
                float a  = __expf(tc[(2 * m) * T_]);
                float cc = __expf(tc[(2 * m + 1) * T_]);
                PACK2(e[m], a, cc);
            }
        }
        const float tstart = trans[START * T_ + j];
        const float tstop  = trans[j * T_ + STOP];

        const float* fb = feats + (size_t)b * (S_ * T_);

        // ---- init: p0 = feat0 + trans[START]; w0 = exp(p0-p0[0]); N = p0[0] ----
        float p0 = fb[j] + tstart;
        if (j == 0) red[h][0] = p0;
        BARH(bar);
        float N = red[h][0];
        float wreg = __expf(p0 - N);
        ws[h][0][j] = wreg;

        const float* fp = fb + T_ + j;
        float fnext = *fp;                   // feat[1], exp'd inside t=1
        int buf = 0;

        for (int t = 1; t < len; ++t) {
            BARH(bar);                       // publishes ws[h][buf]
            const float f = fnext;           // loaded one iteration ago
            const int sel = (t + 1 < S_) ? T_ : 0;
            fp += sel;
            fnext = *fp;                     // LDG for next iteration

            const ulonglong2* vv = (const ulonglong2*)ws[h][buf];
            float w0 = ws[h][buf][0];
            float scale = rcpa(w0) * 0.0078125f;      // 1/(128*w0)
            float ef = __expf(f);                     // overlaps matvec
            N += __logf(w0) + LOG128;                 // off critical path

            unsigned long long a0 = 0, a1 = 0, a2 = 0, a3 = 0;
            unsigned long long a4 = 0, a5 = 0, a6 = 0, a7 = 0;
#pragma unroll
            for (int k = 0; k < 32; k += 4) {
                ulonglong2 x0 = vv[k];
                ulonglong2 x1 = vv[k + 1];
                ulonglong2 x2 = vv[k + 2];
                ulonglong2 x3 = vv[k + 3];
                FMA2(a0, x0.x, e[2 * k],     a0);
                FMA2(a1, x0.y, e[2 * k + 1], a1);
                FMA2(a2, x1.x, e[2 * k + 2], a2);
                FMA2(a3, x1.y, e[2 * k + 3], a3);
                FMA2(a4, x2.x, e[2 * k + 4], a4);
                FMA2(a5, x2.y, e[2 * k + 5], a5);
                FMA2(a6, x3.x, e[2 * k + 6], a6);
                FMA2(a7, x3.y, e[2 * k + 7], a7);
            }
            ADD2(a0, a0, a4); ADD2(a1, a1, a5);
            ADD2(a2, a2, a6); ADD2(a3, a3, a7);
            ADD2(a0, a0, a2); ADD2(a1, a1, a3);
            ADD2(a0, a0, a1);
            float s0, s1;
            UNPACK2(s0, s1, a0);
            wreg = (s0 + s1) * (ef * scale);

            buf ^= 1;
            ws[h][buf][j] = wreg;            // STS before next barrier
        }

        // ---- final: forward = logsumexp_i(p_i + trans[i,STOP]), p = N+log w ----
        float p = N + __logf(wreg);          // -inf for START (w=0): fine in max
        float m = warpMax(p);
        if (lane == 0) red[h][widh] = m;
        BARH(bar);
        m = fmaxf(fmaxf(red[h][0], red[h][1]), fmaxf(red[h][2], red[h][3]));
        float term = wreg * __expf(N - m + tstop);   // exp(p - m + tstop), 0-safe
        term = warpSum(term);
        if (lane == 0) red[h][4 + widh] = term;
        BARH(bar);
        float fwd = m + __logf((red[h][4] + red[h][5]) + (red[h][6] + red[h][7]));

        // ---- gold path score (128 threads of this half) ----
        const long long* t64 = (const long long*)tags_raw;
        const int*       t32 = (const int*)tags_raw;
        const size_t tbase = (size_t)b * S_;
        float g = 0.f;
        for (int tt = j; tt < len; tt += 128) {
            int tag  = is64 ? (int)t64[tbase + tt] : t32[tbase + tt];
            int prev = (tt == 0) ? START
                                 : (is64 ? (int)t64[tbase + tt - 1]
                                         : t32[tbase + tt - 1]);
            g += fb[tt * T_ + tag] + trans[prev * T_ + tag];
        }
        g = warpSum(g);
        if (lane == 0) red[h][8 + widh] = g;
        BARH(bar);

        if (j == 0) {
            int end_id = is64 ? (int)t64[tbase + len - 1] : t32[tbase + len - 1];
            float gold = (red[h][8] + red[h][9]) + (red[h][10] + red[h][11])
                       + trans[end_id * T_ + STOP];
            g_partial[b] = fwd - gold;
            __threadfence();
        }
    }
    __syncthreads();                          // both halves (incl. empty) arrive

    // ---- fused deterministic final reduce (last CTA) ----
    __shared__ unsigned s_rank;
    if (tid == 0) s_rank = atomicAdd(&g_ticket, 1u);
    __syncthreads();
    if (s_rank == NCTA - 1) {
        __threadfence();                      // acquire: see all g_partial
        float x = g_partial[tid];             // 256 threads = 256 batches
        x = warpSum(x);
        __shared__ float sb[8];
        if (lane == 0) sb[tid >> 5] = x;
        __syncthreads();
        if (tid == 0) {
            float s = 0.f;
#pragma unroll
            for (int i = 0; i < 8; ++i) s += sb[i];
            out[0] = s;
            __threadfence();
            atomicExch(&g_ticket, 0u);        // reset for next replay
        }
    }
}

extern "C" void kernel_launch(void* const* d_in, const int* in_sizes, int n_in,
                              void* d_out, int out_size) {
    const float* feats = (const float*)d_in[0];
    const float* trans = (const float*)d_in[1];
    const void*  tags  = d_in[2];
    const int*   mask  = (const int*)d_in[3];

    prep_kernel<<<1, 256>>>(mask);
    crf_kernel<<<NCTA, 256>>>(feats, trans, tags, (float*)d_out);
}

// round 11
// speedup vs baseline: 1.4110x; 1.0215x over previous
#include <cuda_runtime.h>

// CRF NLL, B=256, S=256, T=128 (126 tags + START/STOP)
// grid=148 (1 CTA/SM), 256 threads = two independent 128-thread halves with
// per-half NAMED barriers. prep: 40 longest chains solo, rest paired
// longest-with-shortest (uniform lengths -> near-constant pair sums).
// Scaled-prob recursion, E = exp(transitions) register-resident:
//   w'_j = (sum_i w_i E[i][j]) * exp(f_j) [ / (128*w0) every 4th step ]
//   N accumulates log of applied scales; p_j = N + log w_j at the end.
// Range: per unnorm step w grows <= e^10.5, spread <= e^8 -> |log w| < 45 << 88.

#define B_    256
#define S_    256
#define T_    128
#define NCTA  148
#define NSOLO (2 * NCTA - B_)   // 40
#define LOG128 4.852030263919617f

__device__ float g_partial[B_];
__device__ int   g_slot[2 * NCTA];   // (len << 16) | batch, 0 = empty slot
__device__ unsigned g_ticket;        // zero-init; reset by last CTA

#define FMA2(d, a, b, c) \
    asm("fma.rn.f32x2 %0, %1, %2, %3;" : "=l"(d) : "l"(a), "l"(b), "l"(c))
#define ADD2(d, a, b) \
    asm("add.rn.f32x2 %0, %1, %2;" : "=l"(d) : "l"(a), "l"(b))
#define PACK2(d, lo, hi) \
    asm("mov.b64 %0, {%1, %2};" : "=l"(d) : "f"(lo), "f"(hi))
#define UNPACK2(lo, hi, s) \
    asm("mov.b64 {%0, %1}, %2;" : "=f"(lo), "=f"(hi) : "l"(s))
#define BARH(id) \
    asm volatile("bar.sync %0, 128;" :: "r"(id) : "memory")

__device__ __forceinline__ float rcpa(float x) {
    float r; asm("rcp.approx.f32 %0, %1;" : "=f"(r) : "f"(x)); return r;
}
__device__ __forceinline__ float warpMax(float x) {
#pragma unroll
    for (int o = 16; o; o >>= 1) x = fmaxf(x, __shfl_xor_sync(0xffffffffu, x, o));
    return x;
}
__device__ __forceinline__ float warpSum(float x) {
#pragma unroll
    for (int o = 16; o; o >>= 1) x += __shfl_xor_sync(0xffffffffu, x, o);
    return x;
}

// ---- prep: binary-search lengths, sort desc, build solo/pair schedule ----
__global__ void prep_kernel(const int* __restrict__ mask) {
    __shared__ unsigned key[B_];
    const int b = threadIdx.x;
    const int* mb = mask + b * S_;
    int lo = S_ / 2, hi = S_;               // len in [S/2, S], prefix mask
    while (lo < hi) {                       // 7 iterations
        int mid = (lo + hi) >> 1;
        if (mb[mid]) lo = mid + 1; else hi = mid;
    }
    key[b] = ((unsigned)lo << 16) | (unsigned)b;
    __syncthreads();
    for (int k = 2; k <= B_; k <<= 1) {
        for (int j = k >> 1; j; j >>= 1) {
            int ixj = b ^ j;
            if (ixj > b) {
                unsigned a = key[b], c = key[ixj];
                bool up = (b & k) == 0;     // descending
                if (up ? (a < c) : (a > c)) { key[b] = c; key[ixj] = a; }
            }
            __syncthreads();
        }
    }
    if (b < NCTA) {
        int s0, s1;
        if (b < NSOLO) { s0 = (int)key[b]; s1 = 0; }
        else {
            int k = b - NSOLO;
            s0 = (int)key[NSOLO + k];
            s1 = (int)key[B_ - 1 - k];
        }
        g_slot[2 * b]     = s0;
        g_slot[2 * b + 1] = s1;
    }
}

// One forward step. NORM: rescale by 1/(128*w0) and log it into N.
template <bool NORM>
__device__ __forceinline__ void crf_step(
    const float* __restrict__ wsrc, float* __restrict__ wdst,
    const unsigned long long* __restrict__ e,
    const float*& fp, float& fnext, float& N, float& wreg,
    int t, int j, int bar)
{
    BARH(bar);                               // publishes wsrc
    const float f = fnext;                   // loaded one round ago
    const int sel = (t + 1 < S_) ? T_ : 0;
    fp += sel;
    fnext = *fp;                             // LDG for next round
    const float ef = __expf(f);              // consumed at matvec end

    const ulonglong2* vv = (const ulonglong2*)wsrc;
    unsigned long long a0, a1, a2, a3, a4, a5, a6, a7;
    ulonglong2 x0 = vv[0];
    ulonglong2 x1 = vv[1];
    ulonglong2 x2 = vv[2];
    ulonglong2 x3 = vv[3];

    float mul;
    if (NORM) {
        float w0lo, w0hi;
        UNPACK2(w0lo, w0hi, x0.x);           // w[0] from the first LDS.128
        mul = ef * (rcpa(w0lo) * 0.0078125f);
        N += __logf(w0lo) + LOG128;          // off critical path
    } else {
        mul = ef;
    }

    a0 = a1 = a2 = a3 = a4 = a5 = a6 = a7 = 0ull;
    FMA2(a0, x0.x, e[0], a0);
    FMA2(a1, x0.y, e[1], a1);
    FMA2(a2, x1.x, e[2], a2);
    FMA2(a3, x1.y, e[3], a3);
    FMA2(a4, x2.x, e[4], a4);
    FMA2(a5, x2.y, e[5], a5);
    FMA2(a6, x3.x, e[6], a6);
    FMA2(a7, x3.y, e[7], a7);
#pragma unroll
    for (int k = 4; k < 32; k += 4) {
        ulonglong2 y0 = vv[k];
        ulonglong2 y1 = vv[k + 1];
        ulonglong2 y2 = vv[k + 2];
        ulonglong2 y3 = vv[k + 3];
        FMA2(a0, y0.x, e[2 * k],     a0);
        FMA2(a1, y0.y, e[2 * k + 1], a1);
        FMA2(a2, y1.x, e[2 * k + 2], a2);
        FMA2(a3, y1.y, e[2 * k + 3], a3);
        FMA2(a4, y2.x, e[2 * k + 4], a4);
        FMA2(a5, y2.y, e[2 * k + 5], a5);
        FMA2(a6, y3.x, e[2 * k + 6], a6);
        FMA2(a7, y3.y, e[2 * k + 7], a7);
    }
    ADD2(a0, a0, a4); ADD2(a1, a1, a5);
    ADD2(a2, a2, a6); ADD2(a3, a3, a7);
    ADD2(a0, a0, a2); ADD2(a1, a1, a3);
    ADD2(a0, a0, a1);
    float s0, s1;
    UNPACK2(s0, s1, a0);
    wreg = (s0 + s1) * mul;
    wdst[j] = wreg;                          // STS before next barrier
}

__global__ void __launch_bounds__(256, 1) crf_kernel(
    const float* __restrict__ feats,       // [B, S, T]
    const float* __restrict__ trans,       // [T, T]
    const void*  __restrict__ tags_raw,    // [B, S] int64 OR int32 (auto-detect)
    float* __restrict__ out)
{
    __shared__ __align__(16) float ws[2][2][T_];   // [half][buf][j]
    __shared__ float red[2][12];                   // per-half scratch

    const int tid  = threadIdx.x;
    const int h    = tid >> 7;               // half = chain slot
    const int j    = tid & 127;              // output state
    const int lane = tid & 31;
    const int widh = (tid >> 5) & 3;          // warp within half
    const int bar  = h + 1;                   // named barrier id (1 or 2)
    const int START = T_ - 2, STOP = T_ - 1;

    const int sc  = g_slot[2 * blockIdx.x + h];
    const int b   = sc & 0xFFFF;
    const int len = sc >> 16;                 // 0 => empty slot

    // ---- detect tags dtype (int64 from jax-x64, or silently-demoted int32) ----
    int is64;
    {
        const int* t32 = (const int*)tags_raw;
        int bad = 0;
#pragma unroll
        for (int k = 0; k < 16; ++k) bad |= t32[2 * k + 1];
        is64 = (bad == 0);
    }

    if (len > 0) {
        // ---- E column j in registers: e[m]={exp(tr[2m][j]),exp(tr[2m+1][j])} ----
        unsigned long long e[T_ / 2];
        {
            const float* tc = trans + j;
#pragma unroll
            for (int m = 0; m < T_ / 2; ++m) {
                float a  = __expf(tc[(2 * m) * T_]);
                float cc = __expf(tc[(2 * m + 1) * T_]);
                PACK2(e[m], a, cc);
            }
        }
        const float tstart = trans[START * T_ + j];
        const float tstop  = trans[j * T_ + STOP];

        const float* fb = feats + (size_t)b * (S_ * T_);

        // ---- init: p0 = feat0 + trans[START]; w0 = exp(p0-p0[0]); N = p0[0] ----
        float p0 = fb[j] + tstart;
        if (j == 0) red[h][0] = p0;
        BARH(bar);
        float N = red[h][0];
        float wreg = __expf(p0 - N);
        ws[h][0][j] = wreg;

        const float* fp = fb + T_ + j;
        float fnext = *fp;                   // feat[1]
        int buf = 0, t = 1;

        const int steps = len - 1;
        const int nb4 = steps >> 2;
        const int rem = steps & 3;

        for (int bk = 0; bk < nb4; ++bk) {
            crf_step<true >(ws[h][buf], ws[h][buf ^ 1], e, fp, fnext, N, wreg,
                            t, j, bar);
            buf ^= 1; ++t;
            crf_step<false>(ws[h][buf], ws[h][buf ^ 1], e, fp, fnext, N, wreg,
                            t, j, bar);
            buf ^= 1; ++t;
            crf_step<false>(ws[h][buf], ws[h][buf ^ 1], e, fp, fnext, N, wreg,
                            t, j, bar);
            buf ^= 1; ++t;
            crf_step<false>(ws[h][buf], ws[h][buf ^ 1], e, fp, fnext, N, wreg,
                            t, j, bar);
            buf ^= 1; ++t;
        }
        for (int rr = 0; rr < rem; ++rr) {
            crf_step<true >(ws[h][buf], ws[h][buf ^ 1], e, fp, fnext, N, wreg,
                            t, j, bar);
            buf ^= 1; ++t;
        }

        // ---- final: forward = logsumexp_i(p_i + trans[i,STOP]), p = N+log w ----
        float p = N + __logf(wreg);          // -inf for START (w=0): fine in max
        float m = warpMax(p);
        if (lane == 0) red[h][widh] = m;
        BARH(bar);
        m = fmaxf(fmaxf(red[h][0], red[h][1]), fmaxf(red[h][2], red[h][3]));
        float term = wreg * __expf(N - m + tstop);   // exp(p - m + tstop), 0-safe
        term = warpSum(term);
        if (lane == 0) red[h][4 + widh] = term;
        BARH(bar);
        float fwd = m + __logf((red[h][4] + red[h][5]) + (red[h][6] + red[h][7]));

        // ---- gold path score (128 threads of this half) ----
        const long long* t64 = (const long long*)tags_raw;
        const int*       t32 = (const int*)tags_raw;
        const size_t tbase = (size_t)b * S_;
        float g = 0.f;
        for (int tt = j; tt < len; tt += 128) {
            int tag  = is64 ? (int)t64[tbase + tt] : t32[tbase + tt];
            int prev = (tt == 0) ? START
                                 : (is64 ? (int)t64[tbase + tt - 1]
                                         : t32[tbase + tt - 1]);
            g += fb[tt * T_ + tag] + trans[prev * T_ + tag];
        }
        g = warpSum(g);
        if (lane == 0) red[h][8 + widh] = g;
        BARH(bar);

        if (j == 0) {
            int end_id = is64 ? (int)t64[tbase + len - 1] : t32[tbase + len - 1];
            float gold = (red[h][8] + red[h][9]) + (red[h][10] + red[h][11])
                       + trans[end_id * T_ + STOP];
            g_partial[b] = fwd - gold;
            __threadfence();
        }
    }
    __syncthreads();                          // both halves (incl. empty) arrive

    // ---- fused deterministic final reduce (last CTA) ----
    __shared__ unsigned s_rank;
    if (tid == 0) s_rank = atomicAdd(&g_ticket, 1u);
    __syncthreads();
    if (s_rank == NCTA - 1) {
        __threadfence();                      // acquire: see all g_partial
        float x = g_partial[tid];             // 256 threads = 256 batches
        x = warpSum(x);
        __shared__ float sb[8];
        if (lane == 0) sb[tid >> 5] = x;
        __syncthreads();
        if (tid == 0) {
            float s = 0.f;
#pragma unroll
            for (int i = 0; i < 8; ++i) s += sb[i];
            out[0] = s;
            __threadfence();
            atomicExch(&g_ticket, 0u);        // reset for next replay
        }
    }
}

extern "C" void kernel_launch(void* const* d_in, const int* in_sizes, int n_in,
                              void* d_out, int out_size) {
    const float* feats = (const float*)d_in[0];
    const float* trans = (const float*)d_in[1];
    const void*  tags  = d_in[2];
    const int*   mask  = (const int*)d_in[3];

    prep_kernel<<<1, 256>>>(mask);
    crf_kernel<<<NCTA, 256>>>(feats, trans, tags, (float*)d_out);
}

// round 12
// speedup vs baseline: 1.7166x; 1.2166x over previous
#include <cuda_runtime.h>
#include <cuda_fp16.h>

// CRF NLL, B=256, S=256, T=128 (126 tags + START/STOP)
// grid=148 (1 CTA/SM), 256 threads = two independent 128-thread halves with
// per-half NAMED barriers; 40 longest chains solo, rest paired long+short.
// Matvec datapath in fp16 (HFMA2 rt=2; w vector 256B -> 16 LDS.128):
//   s_j  = sum_i w_i * E[i][j]            (half2 pairs, 8 fp16 accumulators)
//   w'_j = s_j * exp(f_j) / (128*M),  M = max(w[0],w[1],w[64],w[65])
//   N   += log(M) + log128  (fp32);  p_j = N + log w_j at the end (fp32).
// Range: stored w <= ~e^6/128, step sums <= ~1e3 << 65504 (fp16 max).

#define B_    256
#define S_    256
#define T_    128
#define NCTA  148
#define NSOLO (2 * NCTA - B_)   // 40
#define LOG128 4.852030263919617f

__device__ float g_partial[B_];
__device__ int   g_slot[2 * NCTA];   // (len << 16) | batch, 0 = empty slot
__device__ unsigned g_ticket;        // zero-init; reset by last CTA

#define BARH(id) \
    asm volatile("bar.sync %0, 128;" :: "r"(id) : "memory")

__device__ __forceinline__ float rcpa(float x) {
    float r; asm("rcp.approx.f32 %0, %1;" : "=f"(r) : "f"(x)); return r;
}
__device__ __forceinline__ __half2 u2h(unsigned u) {
    __half2 h;
    *reinterpret_cast<unsigned*>(&h) = u;
    return h;
}
__device__ __forceinline__ float warpMax(float x) {
#pragma unroll
    for (int o = 16; o; o >>= 1) x = fmaxf(x, __shfl_xor_sync(0xffffffffu, x, o));
    return x;
}
__device__ __forceinline__ float warpSum(float x) {
#pragma unroll
    for (int o = 16; o; o >>= 1) x += __shfl_xor_sync(0xffffffffu, x, o);
    return x;
}

// ---- prep: binary-search lengths, sort desc, build solo/pair schedule ----
__global__ void prep_kernel(const int* __restrict__ mask) {
    __shared__ unsigned key[B_];
    const int b = threadIdx.x;
    const int* mb = mask + b * S_;
    int lo = S_ / 2, hi = S_;               // len in [S/2, S], prefix mask
    while (lo < hi) {                       // 7 iterations
        int mid = (lo + hi) >> 1;
        if (mb[mid]) lo = mid + 1; else hi = mid;
    }
    key[b] = ((unsigned)lo << 16) | (unsigned)b;
    __syncthreads();
    for (int k = 2; k <= B_; k <<= 1) {
        for (int j = k >> 1; j; j >>= 1) {
            int ixj = b ^ j;
            if (ixj > b) {
                unsigned a = key[b], c = key[ixj];
                bool up = (b & k) == 0;     // descending
                if (up ? (a < c) : (a > c)) { key[b] = c; key[ixj] = a; }
            }
            __syncthreads();
        }
    }
    if (b < NCTA) {
        int s0, s1;
        if (b < NSOLO) { s0 = (int)key[b]; s1 = 0; }
        else {
            int k = b - NSOLO;
            s0 = (int)key[NSOLO + k];
            s1 = (int)key[B_ - 1 - k];
        }
        g_slot[2 * b]     = s0;
        g_slot[2 * b + 1] = s1;
    }
}

// One forward step, fp16 matvec. Always normalizes (fp16 range requires it).
__device__ __forceinline__ void crf_step_h(
    const __half* __restrict__ wsrc, __half* __restrict__ wdst,
    const __half2* __restrict__ eh,
    const float*& fp, float& fnext, float& N, float& wregf,
    int t, int j, int bar)
{
    BARH(bar);                               // publishes wsrc
    const float f = fnext;                   // loaded one round ago
    const int sel = (t + 1 < S_) ? T_ : 0;
    fp += sel;
    fnext = *fp;                             // LDG for next round
    const float ef = __expf(f);              // consumed at matvec end

    const uint4* vv = reinterpret_cast<const uint4*>(wsrc);
    uint4 x0 = vv[0], x1 = vv[1], x2 = vv[2], x3 = vv[3];
    unsigned uw64 = *reinterpret_cast<const unsigned*>(wsrc + 64);

    // robust normalizer: max of w[0], w[1], w[64], w[65]
    __half2 mm = __hmax2(u2h(x0.x), u2h(uw64));
    float M = fmaxf(__low2float(mm), __high2float(mm));
    float scale = rcpa(M) * 0.0078125f;      // 1/(128*M)
    N += __logf(M) + LOG128;                 // off critical path

    __half2 a0 = __hmul2(u2h(x0.x), eh[0]);
    __half2 a1 = __hmul2(u2h(x0.y), eh[1]);
    __half2 a2 = __hmul2(u2h(x0.z), eh[2]);
    __half2 a3 = __hmul2(u2h(x0.w), eh[3]);
    __half2 a4 = __hmul2(u2h(x1.x), eh[4]);
    __half2 a5 = __hmul2(u2h(x1.y), eh[5]);
    __half2 a6 = __hmul2(u2h(x1.z), eh[6]);
    __half2 a7 = __hmul2(u2h(x1.w), eh[7]);
    a0 = __hfma2(u2h(x2.x), eh[8],  a0);
    a1 = __hfma2(u2h(x2.y), eh[9],  a1);
    a2 = __hfma2(u2h(x2.z), eh[10], a2);
    a3 = __hfma2(u2h(x2.w), eh[11], a3);
    a4 = __hfma2(u2h(x3.x), eh[12], a4);
    a5 = __hfma2(u2h(x3.y), eh[13], a5);
    a6 = __hfma2(u2h(x3.z), eh[14], a6);
    a7 = __hfma2(u2h(x3.w), eh[15], a7);
#pragma unroll
    for (int k = 4; k < 16; k += 4) {
        uint4 y0 = vv[k];
        uint4 y1 = vv[k + 1];
        uint4 y2 = vv[k + 2];
        uint4 y3 = vv[k + 3];
        a0 = __hfma2(u2h(y0.x), eh[4 * k + 0],  a0);
        a1 = __hfma2(u2h(y0.y), eh[4 * k + 1],  a1);
        a2 = __hfma2(u2h(y0.z), eh[4 * k + 2],  a2);
        a3 = __hfma2(u2h(y0.w), eh[4 * k + 3],  a3);
        a4 = __hfma2(u2h(y1.x), eh[4 * k + 4],  a4);
        a5 = __hfma2(u2h(y1.y), eh[4 * k + 5],  a5);
        a6 = __hfma2(u2h(y1.z), eh[4 * k + 6],  a6);
        a7 = __hfma2(u2h(y1.w), eh[4 * k + 7],  a7);
        a0 = __hfma2(u2h(y2.x), eh[4 * k + 8],  a0);
        a1 = __hfma2(u2h(y2.y), eh[4 * k + 9],  a1);
        a2 = __hfma2(u2h(y2.z), eh[4 * k + 10], a2);
        a3 = __hfma2(u2h(y2.w), eh[4 * k + 11], a3);
        a4 = __hfma2(u2h(y3.x), eh[4 * k + 12], a4);
        a5 = __hfma2(u2h(y3.y), eh[4 * k + 13], a5);
        a6 = __hfma2(u2h(y3.z), eh[4 * k + 14], a6);
        a7 = __hfma2(u2h(y3.w), eh[4 * k + 15], a7);
    }
    a0 = __hadd2(a0, a4); a1 = __hadd2(a1, a5);
    a2 = __hadd2(a2, a6); a3 = __hadd2(a3, a7);
    a0 = __hadd2(a0, a2); a1 = __hadd2(a1, a3);
    a0 = __hadd2(a0, a1);
    float s = __low2float(a0) + __high2float(a0);

    wregf = s * (ef * scale);
    wdst[j] = __float2half_rn(wregf);        // STS.16 before next barrier
}

__global__ void __launch_bounds__(256, 1) crf_kernel(
    const float* __restrict__ feats,       // [B, S, T]
    const float* __restrict__ trans,       // [T, T]
    const void*  __restrict__ tags_raw,    // [B, S] int64 OR int32 (auto-detect)
    float* __restrict__ out)
{
    __shared__ __align__(16) __half wsh[2][2][T_];   // [half][buf][j]
    __shared__ float red[2][12];                      // per-half scratch

    const int tid  = threadIdx.x;
    const int h    = tid >> 7;               // half = chain slot
    const int j    = tid & 127;              // output state
    const int lane = tid & 31;
    const int widh = (tid >> 5) & 3;          // warp within half
    const int bar  = h + 1;                   // named barrier id (1 or 2)
    const int START = T_ - 2, STOP = T_ - 1;

    const int sc  = g_slot[2 * blockIdx.x + h];
    const int b   = sc & 0xFFFF;
    const int len = sc >> 16;                 // 0 => empty slot

    // ---- detect tags dtype (int64 from jax-x64, or silently-demoted int32) ----
    int is64;
    {
        const int* t32 = (const int*)tags_raw;
        int bad = 0;
#pragma unroll
        for (int k = 0; k < 16; ++k) bad |= t32[2 * k + 1];
        is64 = (bad == 0);
    }

    if (len > 0) {
        // ---- E column j in half2 regs: eh[m]={E[2m][j], E[2m+1][j]} ----
        __half2 eh[T_ / 2];
        {
            const float* tc = trans + j;
#pragma unroll
            for (int m = 0; m < T_ / 2; ++m) {
                float a  = __expf(tc[(2 * m) * T_]);
                float cc = __expf(tc[(2 * m + 1) * T_]);
                eh[m] = __floats2half2_rn(a, cc);
            }
        }
        const float tstart = trans[START * T_ + j];
        const float tstop  = trans[j * T_ + STOP];

        const float* fb = feats + (size_t)b * (S_ * T_);

        // ---- init: p0 = feat0 + trans[START]; w = exp(p0-m0)/128; ----
        // ---- N = m0 + log128 so that p_j = N + log w_j holds.      ----
        float p0 = fb[j] + tstart;
        if (j == 0) red[h][0] = p0;
        BARH(bar);
        const float m0 = red[h][0];
        float N = m0 + LOG128;
        float wregf = __expf(p0 - m0) * 0.0078125f;
        wsh[h][0][j] = __float2half_rn(wregf);

        const float* fp = fb + T_ + j;
        float fnext = *fp;                   // feat[1]
        int buf = 0;

        for (int t = 1; t < len; ++t) {
            crf_step_h(wsh[h][buf], wsh[h][buf ^ 1], eh,
                       fp, fnext, N, wregf, t, j, bar);
            buf ^= 1;
        }

        // ---- final: forward = logsumexp_i(p_i + trans[i,STOP]), p = N+log w ----
        float p = N + __logf(wregf);         // -inf for START (w=0): fine in max
        float m = warpMax(p);
        if (lane == 0) red[h][widh] = m;
        BARH(bar);
        m = fmaxf(fmaxf(red[h][0], red[h][1]), fmaxf(red[h][2], red[h][3]));
        float term = wregf * __expf(N - m + tstop);  // exp(p - m + tstop), 0-safe
        term = warpSum(term);
        if (lane == 0) red[h][4 + widh] = term;
        BARH(bar);
        float fwd = m + __logf((red[h][4] + red[h][5]) + (red[h][6] + red[h][7]));

        // ---- gold path score (128 threads of this half) ----
        const long long* t64 = (const long long*)tags_raw;
        const int*       t32 = (const int*)tags_raw;
        const size_t tbase = (size_t)b * S_;
        float g = 0.f;
        for (int tt = j; tt < len; tt += 128) {
            int tag  = is64 ? (int)t64[tbase + tt] : t32[tbase + tt];
            int prev = (tt == 0) ? START
                                 : (is64 ? (int)t64[tbase + tt - 1]
                                         : t32[tbase + tt - 1]);
            g += fb[tt * T_ + tag] + trans[prev * T_ + tag];
        }
        g = warpSum(g);
        if (lane == 0) red[h][8 + widh] = g;
        BARH(bar);

        if (j == 0) {
            int end_id = is64 ? (int)t64[tbase + len - 1] : t32[tbase + len - 1];
            float gold = (red[h][8] + red[h][9]) + (red[h][10] + red[h][11])
                       + trans[end_id * T_ + STOP];
            g_partial[b] = fwd - gold;
            __threadfence();
        }
    }
    __syncthreads();                          // both halves (incl. empty) arrive

    // ---- fused deterministic final reduce (last CTA) ----
    __shared__ unsigned s_rank;
    if (tid == 0) s_rank = atomicAdd(&g_ticket, 1u);
    __syncthreads();
    if (s_rank == NCTA - 1) {
        __threadfence();                      // acquire: see all g_partial
        float x = g_partial[tid];             // 256 threads = 256 batches
        x = warpSum(x);
        __shared__ float sb[8];
        if (lane == 0) sb[tid >> 5] = x;
        __syncthreads();
        if (tid == 0) {
            float s = 0.f;
#pragma unroll
            for (int i = 0; i < 8; ++i) s += sb[i];
            out[0] = s;
            __threadfence();
            atomicExch(&g_ticket, 0u);        // reset for next replay
        }
    }
}

extern "C" void kernel_launch(void* const* d_in, const int* in_sizes, int n_in,
                              void* d_out, int out_size) {
    const float* feats = (const float*)d_in[0];
    const float* trans = (const float*)d_in[1];
    const void*  tags  = d_in[2];
    const int*   mask  = (const int*)d_in[3];

    prep_kernel<<<1, 256>>>(mask);
    crf_kernel<<<NCTA, 256>>>(feats, trans, tags, (float*)d_out);
}